// round 2
// baseline (speedup 1.0000x reference)
#include <cuda_runtime.h>
#include <math.h>

// DiagBlockAttention: b=16, t=8192, e=256, block=128.
// Per 128-token block: S = (Qb Kb^T)/16, causal mask within block, softmax,
// O = A Vb. Outputs: O [b,t,e] fp32 then A_flat [b,t,128] fp32 (concatenated).

namespace {
constexpr int Tt  = 8192;
constexpr int Ee  = 256;
constexpr int BSz = 128;
constexpr int NBk = Tt / BSz;   // 64
constexpr int EC  = 16;         // e-chunk for phase 1
constexpr int AS_STRIDE = 132;  // padded stride for A in smem
constexpr int SMEM_FLOATS = BSz * AS_STRIDE + BSz * BSz;  // A tile + workspace
constexpr int SMEM_BYTES  = SMEM_FLOATS * 4;              // 133120 B
}

__global__ void __launch_bounds__(256, 1)
diag_block_attn(const float* __restrict__ Q, const float* __restrict__ K,
                const float* __restrict__ V, float* __restrict__ Out,
                float* __restrict__ Afl)
{
    extern __shared__ float sm[];
    float* As = sm;                       // [128][AS_STRIDE] row-major A
    float* W  = sm + BSz * AS_STRIDE;    // 128*128 workspace (Qc/Kc then Vc)

    const int n   = blockIdx.x;
    const int b   = blockIdx.y;
    const int tid = threadIdx.x;
    const int tx  = tid & 15;
    const int ty  = tid >> 4;
    const int r0  = ty * 8;
    const int c0  = tx * 8;
    const long base = ((long)b * Tt + (long)n * BSz) * Ee;

    float acc[8][8];
    #pragma unroll
    for (int i = 0; i < 8; ++i)
        #pragma unroll
        for (int j = 0; j < 8; ++j) acc[i][j] = 0.f;

    float* Qc = W;               // [EC][128] transposed chunk
    float* Kc = W + EC * BSz;    // [EC][128]

    // ---------------- Phase 1: S = Q K^T ----------------
    for (int e0 = 0; e0 < Ee; e0 += EC) {
        #pragma unroll
        for (int it = 0; it < 2; ++it) {
            int idx = it * 256 + tid;       // 0..511
            int r   = idx >> 2;             // 0..127
            int c4  = (idx & 3) << 2;       // 0,4,8,12
            const float4 q = *reinterpret_cast<const float4*>(Q + base + (long)r * Ee + e0 + c4);
            const float4 k = *reinterpret_cast<const float4*>(K + base + (long)r * Ee + e0 + c4);
            Qc[(c4 + 0) * BSz + r] = q.x; Qc[(c4 + 1) * BSz + r] = q.y;
            Qc[(c4 + 2) * BSz + r] = q.z; Qc[(c4 + 3) * BSz + r] = q.w;
            Kc[(c4 + 0) * BSz + r] = k.x; Kc[(c4 + 1) * BSz + r] = k.y;
            Kc[(c4 + 2) * BSz + r] = k.z; Kc[(c4 + 3) * BSz + r] = k.w;
        }
        __syncthreads();
        #pragma unroll
        for (int ee = 0; ee < EC; ++ee) {
            const float4 a0 = *reinterpret_cast<const float4*>(Qc + ee * BSz + r0);
            const float4 a1 = *reinterpret_cast<const float4*>(Qc + ee * BSz + r0 + 4);
            const float4 b0 = *reinterpret_cast<const float4*>(Kc + ee * BSz + c0);
            const float4 b1 = *reinterpret_cast<const float4*>(Kc + ee * BSz + c0 + 4);
            const float aR[8] = {a0.x, a0.y, a0.z, a0.w, a1.x, a1.y, a1.z, a1.w};
            const float bR[8] = {b0.x, b0.y, b0.z, b0.w, b1.x, b1.y, b1.z, b1.w};
            #pragma unroll
            for (int i = 0; i < 8; ++i)
                #pragma unroll
                for (int j = 0; j < 8; ++j)
                    acc[i][j] = fmaf(aR[i], bR[j], acc[i][j]);
        }
        __syncthreads();
    }

    // ---------------- Phase 2: mask + softmax ----------------
    const float scale = 0.0625f;  // 1/sqrt(256)
    float inv[8];
    #pragma unroll
    for (int i = 0; i < 8; ++i) {
        const int r = r0 + i;
        float mx = -INFINITY;
        #pragma unroll
        for (int j = 0; j < 8; ++j) {
            const int c = c0 + j;
            float v = (c <= r) ? acc[i][j] * scale : -INFINITY;
            acc[i][j] = v;
            mx = fmaxf(mx, v);
        }
        #pragma unroll
        for (int o = 1; o < 16; o <<= 1)
            mx = fmaxf(mx, __shfl_xor_sync(0xffffffffu, mx, o));
        float s = 0.f;
        #pragma unroll
        for (int j = 0; j < 8; ++j) {
            // exp(-inf - mx) -> 0 for masked entries
            float p = __expf(acc[i][j] - mx);
            acc[i][j] = p;
            s += p;
        }
        #pragma unroll
        for (int o = 1; o < 16; o <<= 1)
            s += __shfl_xor_sync(0xffffffffu, s, o);
        inv[i] = 1.f / s;
    }

    // Normalize; write A to smem (row-major) and to global A_flat.
    #pragma unroll
    for (int i = 0; i < 8; ++i) {
        #pragma unroll
        for (int j = 0; j < 8; ++j) acc[i][j] *= inv[i];
        float4 w0 = make_float4(acc[i][0], acc[i][1], acc[i][2], acc[i][3]);
        float4 w1 = make_float4(acc[i][4], acc[i][5], acc[i][6], acc[i][7]);
        *reinterpret_cast<float4*>(As + (r0 + i) * AS_STRIDE + c0)     = w0;
        *reinterpret_cast<float4*>(As + (r0 + i) * AS_STRIDE + c0 + 4) = w1;
        if (Afl) {
            float* ag = Afl + ((long)b * Tt + (long)n * BSz + (r0 + i)) * BSz + c0;
            *reinterpret_cast<float4*>(ag)     = w0;
            *reinterpret_cast<float4*>(ag + 4) = w1;
        }
    }

    // ---------------- Phase 3: O = A V (two 128-col halves) ----------------
    float* Vc = W;   // [128][128]
    #pragma unroll 1
    for (int h = 0; h < 2; ++h) {
        __syncthreads();  // As written (h=0) / prior Vc reads done (h=1)
        #pragma unroll
        for (int it = 0; it < 16; ++it) {
            int idx = it * 256 + tid;      // 0..4095 : full 128x128 tile in float4s
            int r   = idx >> 5;            // 0..127
            int c4  = (idx & 31) << 2;     // 0..124
            *reinterpret_cast<float4*>(Vc + r * BSz + c4) =
                *reinterpret_cast<const float4*>(V + base + (long)r * Ee + h * BSz + c4);
        }
        __syncthreads();

        float o[8][8];
        #pragma unroll
        for (int i = 0; i < 8; ++i)
            #pragma unroll
            for (int j = 0; j < 8; ++j) o[i][j] = 0.f;

        for (int k = 0; k < BSz; ++k) {
            float aR[8];
            #pragma unroll
            for (int i = 0; i < 8; ++i) aR[i] = As[(r0 + i) * AS_STRIDE + k];
            const float4 b0 = *reinterpret_cast<const float4*>(Vc + k * BSz + c0);
            const float4 b1 = *reinterpret_cast<const float4*>(Vc + k * BSz + c0 + 4);
            const float bR[8] = {b0.x, b0.y, b0.z, b0.w, b1.x, b1.y, b1.z, b1.w};
            #pragma unroll
            for (int i = 0; i < 8; ++i)
                #pragma unroll
                for (int j = 0; j < 8; ++j)
                    o[i][j] = fmaf(aR[i], bR[j], o[i][j]);
        }

        #pragma unroll
        for (int i = 0; i < 8; ++i) {
            float* og = Out + base + (long)(r0 + i) * Ee + h * BSz + c0;
            *reinterpret_cast<float4*>(og) =
                make_float4(o[i][0], o[i][1], o[i][2], o[i][3]);
            *reinterpret_cast<float4*>(og + 4) =
                make_float4(o[i][4], o[i][5], o[i][6], o[i][7]);
        }
    }
}

extern "C" void kernel_launch(void* const* d_in, const int* in_sizes, int n_in,
                              void* d_out, int out_size)
{
    const float* Q = (const float*)d_in[0];
    const float* K = (const float*)d_in[1];
    const float* V = (const float*)d_in[2];
    float* out = (float*)d_out;

    const int b = in_sizes[0] / (Tt * Ee);          // 16
    const long out_elems = (long)b * Tt * Ee;       // O part
    const long a_elems   = (long)b * Tt * BSz;      // A part
    float* Afl = ((long)out_size >= out_elems + a_elems) ? (out + out_elems) : nullptr;

    cudaFuncSetAttribute(diag_block_attn,
                         cudaFuncAttributeMaxDynamicSharedMemorySize, SMEM_BYTES);
    dim3 grid(NBk, b);
    diag_block_attn<<<grid, 256, SMEM_BYTES>>>(Q, K, V, out, Afl);
}

// round 3
// speedup vs baseline: 1.3795x; 1.3795x over previous
#include <cuda_runtime.h>
#include <math.h>

// DiagBlockAttention: b=16, t=8192, e=256, block=128.
// Outputs: O [b,t,256] fp32 then A_flat [b,t,128] fp32 (concatenated in d_out).

namespace {
constexpr int Tt  = 8192;
constexpr int Ee  = 256;
constexpr int BSz = 128;
constexpr int NBk = Tt / BSz;   // 64
constexpr int EC  = 16;         // e-chunk for phase 1
constexpr int VC  = 64;         // v-column chunk for phase 3
constexpr int AS_STRIDE = 132;  // padded stride for A in smem
constexpr int AS_FLOATS = BSz * AS_STRIDE;          // 16896
constexpr int W_FLOATS  = BSz * VC;                 // 8192 (>= 2*EC*BSz = 4096)
constexpr int SMEM_FLOATS = AS_FLOATS + W_FLOATS;   // 25088
constexpr int SMEM_BYTES  = SMEM_FLOATS * 4;        // 100352 B -> 2 CTAs/SM
}

#define FMA2(d, a, b, c) \
    asm("fma.rn.f32x2 %0, %1, %2, %3;" : "=l"(d) : "l"(a), "l"(b), "l"(c))
#define PACK2(d, lo, hi) \
    asm("mov.b64 %0, {%1, %2};" : "=l"(d) : "r"(lo), "r"(hi))
#define DUP2(d, x) \
    asm("mov.b64 %0, {%1, %1};" : "=l"(d) : "r"(x))
#define UNPACK2(lo, hi, in) \
    asm("mov.b64 {%0, %1}, %2;" : "=r"(lo), "=r"(hi) : "l"(in))

__global__ void __launch_bounds__(256, 2)
diag_block_attn(const float* __restrict__ Q, const float* __restrict__ K,
                const float* __restrict__ V, float* __restrict__ Out,
                float* __restrict__ Afl)
{
    extern __shared__ float sm[];
    float* As = sm;                 // [128][AS_STRIDE]
    float* W  = sm + AS_FLOATS;     // phase1: Qc/Kc; phase3: Vc [128][VC]

    const int n   = blockIdx.x;
    const int b   = blockIdx.y;
    const int tid = threadIdx.x;
    const int tx  = tid & 15;
    const int ty  = tid >> 4;
    const int r0  = ty * 8;
    const int c0  = tx * 8;          // S-tile cols (phase 1/2)
    const long base = ((long)b * Tt + (long)n * BSz) * Ee;

    unsigned long long accP[8][4];
    #pragma unroll
    for (int i = 0; i < 8; ++i)
        #pragma unroll
        for (int jp = 0; jp < 4; ++jp) accP[i][jp] = 0ull;

    float* Qc = W;               // [EC][128] transposed chunk
    float* Kc = W + EC * BSz;    // [EC][128]

    // ---------------- Phase 1: S = Q K^T (f32x2) ----------------
    for (int e0 = 0; e0 < Ee; e0 += EC) {
        #pragma unroll
        for (int it = 0; it < 2; ++it) {
            int idx = it * 256 + tid;       // 0..511
            int r   = idx >> 2;             // 0..127
            int c4  = (idx & 3) << 2;       // 0,4,8,12
            const float4 q = *reinterpret_cast<const float4*>(Q + base + (long)r * Ee + e0 + c4);
            const float4 k = *reinterpret_cast<const float4*>(K + base + (long)r * Ee + e0 + c4);
            Qc[(c4 + 0) * BSz + r] = q.x; Qc[(c4 + 1) * BSz + r] = q.y;
            Qc[(c4 + 2) * BSz + r] = q.z; Qc[(c4 + 3) * BSz + r] = q.w;
            Kc[(c4 + 0) * BSz + r] = k.x; Kc[(c4 + 1) * BSz + r] = k.y;
            Kc[(c4 + 2) * BSz + r] = k.z; Kc[(c4 + 3) * BSz + r] = k.w;
        }
        __syncthreads();
        #pragma unroll
        for (int ee = 0; ee < EC; ++ee) {
            const float4 a0 = *reinterpret_cast<const float4*>(Qc + ee * BSz + r0);
            const float4 a1 = *reinterpret_cast<const float4*>(Qc + ee * BSz + r0 + 4);
            const float4 b0 = *reinterpret_cast<const float4*>(Kc + ee * BSz + c0);
            const float4 b1 = *reinterpret_cast<const float4*>(Kc + ee * BSz + c0 + 4);
            unsigned long long bp[4];
            PACK2(bp[0], __float_as_uint(b0.x), __float_as_uint(b0.y));
            PACK2(bp[1], __float_as_uint(b0.z), __float_as_uint(b0.w));
            PACK2(bp[2], __float_as_uint(b1.x), __float_as_uint(b1.y));
            PACK2(bp[3], __float_as_uint(b1.z), __float_as_uint(b1.w));
            const float aR[8] = {a0.x, a0.y, a0.z, a0.w, a1.x, a1.y, a1.z, a1.w};
            #pragma unroll
            for (int i = 0; i < 8; ++i) {
                unsigned long long ap;
                DUP2(ap, __float_as_uint(aR[i]));
                #pragma unroll
                for (int jp = 0; jp < 4; ++jp)
                    FMA2(accP[i][jp], ap, bp[jp], accP[i][jp]);
            }
        }
        __syncthreads();
    }

    // ---------------- Phase 2: mask + softmax ----------------
    float acc[8][8];
    #pragma unroll
    for (int i = 0; i < 8; ++i)
        #pragma unroll
        for (int jp = 0; jp < 4; ++jp) {
            unsigned int lo, hi;
            UNPACK2(lo, hi, accP[i][jp]);
            acc[i][2 * jp]     = __uint_as_float(lo);
            acc[i][2 * jp + 1] = __uint_as_float(hi);
        }

    const float scale = 0.0625f;  // 1/sqrt(256)
    #pragma unroll
    for (int i = 0; i < 8; ++i) {
        const int r = r0 + i;
        float mx = -INFINITY;
        #pragma unroll
        for (int j = 0; j < 8; ++j) {
            const int c = c0 + j;
            float v = (c <= r) ? acc[i][j] * scale : -INFINITY;
            acc[i][j] = v;
            mx = fmaxf(mx, v);
        }
        #pragma unroll
        for (int o = 1; o < 16; o <<= 1)
            mx = fmaxf(mx, __shfl_xor_sync(0xffffffffu, mx, o));
        float s = 0.f;
        #pragma unroll
        for (int j = 0; j < 8; ++j) {
            float p = __expf(acc[i][j] - mx);  // exp(-inf) -> 0 for masked
            acc[i][j] = p;
            s += p;
        }
        #pragma unroll
        for (int o = 1; o < 16; o <<= 1)
            s += __shfl_xor_sync(0xffffffffu, s, o);
        const float inv = 1.f / s;
        #pragma unroll
        for (int j = 0; j < 8; ++j) acc[i][j] *= inv;

        float4 w0 = make_float4(acc[i][0], acc[i][1], acc[i][2], acc[i][3]);
        float4 w1 = make_float4(acc[i][4], acc[i][5], acc[i][6], acc[i][7]);
        *reinterpret_cast<float4*>(As + r * AS_STRIDE + c0)     = w0;
        *reinterpret_cast<float4*>(As + r * AS_STRIDE + c0 + 4) = w1;
        if (Afl) {
            float* ag = Afl + ((long)b * Tt + (long)n * BSz + r) * BSz + c0;
            *reinterpret_cast<float4*>(ag)     = w0;
            *reinterpret_cast<float4*>(ag + 4) = w1;
        }
    }
    __syncthreads();  // As visible to all; phase-1 W reads complete

    // ---------------- Phase 3: O = A V, four 64-col chunks ----------------
    float* Vc = W;                   // [128][VC]
    const int cx = tx * 4;           // 4 output cols per thread within chunk
    #pragma unroll 1
    for (int h = 0; h < 4; ++h) {
        #pragma unroll
        for (int it = 0; it < 8; ++it) {
            int idx = it * 256 + tid;       // 0..2047
            int r   = idx >> 4;             // 0..127
            int c4  = (idx & 15) << 2;      // 0..60
            *reinterpret_cast<float4*>(Vc + r * VC + c4) =
                *reinterpret_cast<const float4*>(V + base + (long)r * Ee + h * VC + c4);
        }
        __syncthreads();

        unsigned long long o2[8][2];
        #pragma unroll
        for (int i = 0; i < 8; ++i) { o2[i][0] = 0ull; o2[i][1] = 0ull; }

        #pragma unroll 4
        for (int k = 0; k < BSz; ++k) {
            const float4 v = *reinterpret_cast<const float4*>(Vc + k * VC + cx);
            unsigned long long vp[2];
            PACK2(vp[0], __float_as_uint(v.x), __float_as_uint(v.y));
            PACK2(vp[1], __float_as_uint(v.z), __float_as_uint(v.w));
            #pragma unroll
            for (int i = 0; i < 8; ++i) {
                unsigned long long ap;
                DUP2(ap, __float_as_uint(As[(r0 + i) * AS_STRIDE + k]));
                FMA2(o2[i][0], ap, vp[0], o2[i][0]);
                FMA2(o2[i][1], ap, vp[1], o2[i][1]);
            }
        }

        #pragma unroll
        for (int i = 0; i < 8; ++i) {
            unsigned int x0, x1, x2, x3;
            UNPACK2(x0, x1, o2[i][0]);
            UNPACK2(x2, x3, o2[i][1]);
            float* og = Out + base + (long)(r0 + i) * Ee + h * VC + cx;
            *reinterpret_cast<float4*>(og) =
                make_float4(__uint_as_float(x0), __uint_as_float(x1),
                            __uint_as_float(x2), __uint_as_float(x3));
        }
        __syncthreads();  // Vc reads done before next chunk overwrites
    }
}

extern "C" void kernel_launch(void* const* d_in, const int* in_sizes, int n_in,
                              void* d_out, int out_size)
{
    const float* Q = (const float*)d_in[0];
    const float* K = (const float*)d_in[1];
    const float* V = (const float*)d_in[2];
    float* out = (float*)d_out;

    const int b = in_sizes[0] / (Tt * Ee);
    const long out_elems = (long)b * Tt * Ee;
    const long a_elems   = (long)b * Tt * BSz;
    float* Afl = ((long)out_size >= out_elems + a_elems) ? (out + out_elems) : nullptr;

    cudaFuncSetAttribute(diag_block_attn,
                         cudaFuncAttributeMaxDynamicSharedMemorySize, SMEM_BYTES);
    dim3 grid(NBk, b);
    diag_block_attn<<<grid, 256, SMEM_BYTES>>>(Q, K, V, out, Afl);
}

// round 5
// speedup vs baseline: 2.2350x; 1.6201x over previous
#include <cuda_runtime.h>
#include <cuda_bf16.h>
#include <cstdint>
#include <math.h>

// DiagBlockAttention b=16,t=8192,e=256,block=128 — mma.sync bf16 hi/lo split.
// d_out = O [b,t,256] fp32 ++ A_flat [b,t,128] fp32.

namespace {
constexpr int Tt = 8192, Ee = 256, BSz = 128, NBk = 64;
constexpr float SCALE = 0.0625f;

// SMEM byte map
constexpr int RED_M = 0;          // 256 f32
constexpr int RED_S = 1024;       // 256 f32
constexpr int REG0  = 2048;
// phase 1: Q/K hi/lo tiles [128 rows][64 cols] bf16, 128B rows (swz128)
constexpr int QH = REG0, QL = REG0 + 16384, KHs = REG0 + 32768, KLs = REG0 + 49152;
// phase 3: A hi/lo [128 m][128 k] bf16, 256B rows (swz256) — overlaps Q/K
constexpr int AHs = REG0, ALs = REG0 + 32768;
// phase 3: V^T hi/lo [64 e][128 tok] bf16, 256B rows (swz256)
constexpr int VHs = REG0 + 65536, VLs = REG0 + 81920;
constexpr int SMEM_BYTES = REG0 + 98304;   // 100352 -> 2 CTAs/SM
}

__device__ __forceinline__ uint32_t swz128(uint32_t o) { return o ^ ((o >> 3) & 0x70u); }
__device__ __forceinline__ uint32_t swz256(uint32_t o) { return o ^ ((o >> 4) & 0x70u); }

__device__ __forceinline__ uint32_t smem_u32(const void* p) {
    uint32_t a;
    asm("{ .reg .u64 t; cvta.to.shared.u64 t, %1; cvt.u32.u64 %0, t; }" : "=r"(a) : "l"(p));
    return a;
}

__device__ __forceinline__ void ldmx4(uint32_t r[4], uint32_t addr) {
    asm volatile("ldmatrix.sync.aligned.m8n8.x4.shared.b16 {%0,%1,%2,%3}, [%4];"
                 : "=r"(r[0]), "=r"(r[1]), "=r"(r[2]), "=r"(r[3]) : "r"(addr));
}

__device__ __forceinline__ void mma16816(float c[4], const uint32_t a[4],
                                         uint32_t b0, uint32_t b1) {
    asm volatile("mma.sync.aligned.m16n8k16.row.col.f32.bf16.bf16.f32 "
                 "{%0,%1,%2,%3},{%4,%5,%6,%7},{%8,%9},{%0,%1,%2,%3};"
                 : "+f"(c[0]), "+f"(c[1]), "+f"(c[2]), "+f"(c[3])
                 : "r"(a[0]), "r"(a[1]), "r"(a[2]), "r"(a[3]), "r"(b0), "r"(b1));
}

// Split two fp32 into packed bf16x2 hi and lo (residual) parts.
__device__ __forceinline__ void split2(float x, float y, uint32_t& H, uint32_t& L) {
    __nv_bfloat16 hx = __float2bfloat16(x), hy = __float2bfloat16(y);
    __nv_bfloat16 lx = __float2bfloat16(x - __bfloat162float(hx));
    __nv_bfloat16 ly = __float2bfloat16(y - __bfloat162float(hy));
    __nv_bfloat162 Hp(hx, hy), Lp(lx, ly);
    H = *reinterpret_cast<uint32_t*>(&Hp);
    L = *reinterpret_cast<uint32_t*>(&Lp);
}

__global__ void __launch_bounds__(256, 2)
diag_block_attn_mma(const float* __restrict__ Q, const float* __restrict__ K,
                    const float* __restrict__ V, float* __restrict__ Out,
                    float* __restrict__ Afl)
{
    extern __shared__ char smc[];
    const uint32_t sb = smem_u32(smc);
    float* redM = reinterpret_cast<float*>(smc + RED_M);
    float* redS = reinterpret_cast<float*>(smc + RED_S);

    const int tid = threadIdx.x;
    const int wid = tid >> 5;
    const int lid = tid & 31;
    const int g   = lid >> 2;       // row group within mma tile
    const int tg  = lid & 3;        // col quad
    const int wm  = wid >> 1;       // warp row (0..3): rows wm*32..+31
    const int wn  = wid & 1;        // warp col (0..1)
    const int lr  = lid & 15;       // ldmatrix row lane
    const int lc  = (lid >> 4) * 8; // ldmatrix col-block (elements)
    const int n   = blockIdx.x;
    const int b   = blockIdx.y;
    const long base = ((long)b * Tt + (long)n * BSz) * Ee;

    // ================= Phase 1: S = Q K^T (3-pass hi/lo) =================
    float acc[2][8][4];
    #pragma unroll
    for (int mt = 0; mt < 2; ++mt)
        #pragma unroll
        for (int nt = 0; nt < 8; ++nt)
            #pragma unroll
            for (int cc = 0; cc < 4; ++cc) acc[mt][nt][cc] = 0.f;

    for (int c = 0; c < 4; ++c) {
        const float* Qg = Q + base + c * 64;
        const float* Kg = K + base + c * 64;
        #pragma unroll
        for (int u = 0; u < 8; ++u) {
            int idx = tid + 256 * u;          // 0..2047
            int r   = idx >> 4;               // 0..127
            int ce  = (idx & 15) << 2;        // 0..60
            float4 q = *reinterpret_cast<const float4*>(Qg + (long)r * Ee + ce);
            float4 k = *reinterpret_cast<const float4*>(Kg + (long)r * Ee + ce);
            uint32_t qh0, ql0, qh1, ql1, kh0, kl0, kh1, kl1;
            split2(q.x, q.y, qh0, ql0); split2(q.z, q.w, qh1, ql1);
            split2(k.x, k.y, kh0, kl0); split2(k.z, k.w, kh1, kl1);
            uint32_t off = swz128((uint32_t)(r * 128 + ce * 2));
            *reinterpret_cast<uint2*>(smc + QH  + off) = make_uint2(qh0, qh1);
            *reinterpret_cast<uint2*>(smc + QL  + off) = make_uint2(ql0, ql1);
            *reinterpret_cast<uint2*>(smc + KHs + off) = make_uint2(kh0, kh1);
            *reinterpret_cast<uint2*>(smc + KLs + off) = make_uint2(kl0, kl1);
        }
        __syncthreads();

        #pragma unroll
        for (int ks = 0; ks < 4; ++ks) {
            const int colB = (lc + ks * 16) * 2;   // byte col
            uint32_t qhf[2][4], qlf[2][4];
            #pragma unroll
            for (int mt = 0; mt < 2; ++mt) {
                uint32_t off = swz128((uint32_t)((wm * 32 + mt * 16 + lr) * 128 + colB));
                ldmx4(qhf[mt], sb + QH + off);
                ldmx4(qlf[mt], sb + QL + off);
            }
            #pragma unroll
            for (int ng = 0; ng < 4; ++ng) {
                uint32_t off = swz128((uint32_t)((wn * 64 + ng * 16 + lr) * 128 + colB));
                uint32_t kh4[4], kl4[4];
                ldmx4(kh4, sb + KHs + off);
                ldmx4(kl4, sb + KLs + off);
                #pragma unroll
                for (int mt = 0; mt < 2; ++mt) {
                    mma16816(acc[mt][2 * ng],     qhf[mt], kh4[0], kh4[2]);
                    mma16816(acc[mt][2 * ng + 1], qhf[mt], kh4[1], kh4[3]);
                    mma16816(acc[mt][2 * ng],     qhf[mt], kl4[0], kl4[2]);
                    mma16816(acc[mt][2 * ng + 1], qhf[mt], kl4[1], kl4[3]);
                    mma16816(acc[mt][2 * ng],     qlf[mt], kh4[0], kh4[2]);
                    mma16816(acc[mt][2 * ng + 1], qlf[mt], kh4[1], kh4[3]);
                }
            }
        }
        __syncthreads();
    }

    // ================= Phase 2: mask + softmax =================
    float rmax[2][2] = {{-INFINITY, -INFINITY}, {-INFINITY, -INFINITY}};
    #pragma unroll
    for (int mt = 0; mt < 2; ++mt)
        #pragma unroll
        for (int nt = 0; nt < 8; ++nt)
            #pragma unroll
            for (int cc = 0; cc < 4; ++cc) {
                int row = wm * 32 + mt * 16 + (cc >> 1) * 8 + g;
                int col = wn * 64 + nt * 8 + 2 * tg + (cc & 1);
                float v = (col <= row) ? acc[mt][nt][cc] * SCALE : -INFINITY;
                acc[mt][nt][cc] = v;
                rmax[mt][cc >> 1] = fmaxf(rmax[mt][cc >> 1], v);
            }
    #pragma unroll
    for (int mt = 0; mt < 2; ++mt)
        #pragma unroll
        for (int rh = 0; rh < 2; ++rh) {
            float v = rmax[mt][rh];
            v = fmaxf(v, __shfl_xor_sync(0xffffffffu, v, 1));
            v = fmaxf(v, __shfl_xor_sync(0xffffffffu, v, 2));
            if (tg == 0) redM[wn * 128 + wm * 32 + mt * 16 + rh * 8 + g] = v;
        }
    __syncthreads();

    float rm[2][2], rsum[2][2] = {{0.f, 0.f}, {0.f, 0.f}};
    #pragma unroll
    for (int mt = 0; mt < 2; ++mt)
        #pragma unroll
        for (int rh = 0; rh < 2; ++rh) {
            int row = wm * 32 + mt * 16 + rh * 8 + g;
            rm[mt][rh] = fmaxf(redM[row], redM[128 + row]);
        }
    #pragma unroll
    for (int mt = 0; mt < 2; ++mt)
        #pragma unroll
        for (int nt = 0; nt < 8; ++nt)
            #pragma unroll
            for (int cc = 0; cc < 4; ++cc) {
                float p = __expf(acc[mt][nt][cc] - rm[mt][cc >> 1]);
                acc[mt][nt][cc] = p;
                rsum[mt][cc >> 1] += p;
            }
    #pragma unroll
    for (int mt = 0; mt < 2; ++mt)
        #pragma unroll
        for (int rh = 0; rh < 2; ++rh) {
            float s = rsum[mt][rh];
            s += __shfl_xor_sync(0xffffffffu, s, 1);
            s += __shfl_xor_sync(0xffffffffu, s, 2);
            if (tg == 0) redS[wn * 128 + wm * 32 + mt * 16 + rh * 8 + g] = s;
        }
    __syncthreads();

    float rinv[2][2];
    #pragma unroll
    for (int mt = 0; mt < 2; ++mt)
        #pragma unroll
        for (int rh = 0; rh < 2; ++rh) {
            int row = wm * 32 + mt * 16 + rh * 8 + g;
            rinv[mt][rh] = 1.f / (redS[row] + redS[128 + row]);
        }

    // Normalize; A -> gmem (fp32) and smem hi/lo bf16 (overwrites Q/K tiles —
    // safe: all warps passed the redM barrier after their last ldmatrix).
    #pragma unroll
    for (int mt = 0; mt < 2; ++mt)
        #pragma unroll
        for (int nt = 0; nt < 8; ++nt)
            #pragma unroll
            for (int rh = 0; rh < 2; ++rh) {
                float a0 = acc[mt][nt][rh * 2]     * rinv[mt][rh];
                float a1 = acc[mt][nt][rh * 2 + 1] * rinv[mt][rh];
                int row = wm * 32 + mt * 16 + rh * 8 + g;
                int col = wn * 64 + nt * 8 + 2 * tg;
                uint32_t H, L;
                split2(a0, a1, H, L);
                uint32_t off = swz256((uint32_t)(row * 256 + col * 2));
                *reinterpret_cast<uint32_t*>(smc + AHs + off) = H;
                *reinterpret_cast<uint32_t*>(smc + ALs + off) = L;
                if (Afl) {
                    float2 w = make_float2(a0, a1);
                    *reinterpret_cast<float2*>(
                        Afl + ((long)b * Tt + (long)n * BSz + row) * BSz + col) = w;
                }
            }
    __syncthreads();

    // ================= Phase 3: O = A V (4 e-chunks of 64) =================
    #pragma unroll 1
    for (int nc = 0; nc < 4; ++nc) {
        // Stage V^T hi/lo for e in [nc*64, nc*64+64): Vt[e][token]
        #pragma unroll
        for (int u = 0; u < 4; ++u) {
            int unit = tid + 256 * u;        // 0..1023
            int l    = unit & 31;
            int grp  = unit >> 5;            // 0..31
            int c4i  = grp & 15, khi = grp >> 4;
            int k    = 2 * l + 64 * khi;     // even token
            int e0   = 4 * c4i;
            const float* vg = V + base + (long)k * Ee + nc * 64 + e0;
            float4 v0 = *reinterpret_cast<const float4*>(vg);
            float4 v1 = *reinterpret_cast<const float4*>(vg + Ee);
            const float* a0 = reinterpret_cast<const float*>(&v0);
            const float* a1 = reinterpret_cast<const float*>(&v1);
            #pragma unroll
            for (int j = 0; j < 4; ++j) {
                uint32_t H, L;
                split2(a0[j], a1[j], H, L);
                uint32_t off = swz256((uint32_t)((e0 + j) * 256 + k * 2));
                *reinterpret_cast<uint32_t*>(smc + VHs + off) = H;
                *reinterpret_cast<uint32_t*>(smc + VLs + off) = L;
            }
        }
        __syncthreads();

        float o3[2][4][4];
        #pragma unroll
        for (int mt = 0; mt < 2; ++mt)
            #pragma unroll
            for (int nt = 0; nt < 4; ++nt)
                #pragma unroll
                for (int cc = 0; cc < 4; ++cc) o3[mt][nt][cc] = 0.f;

        #pragma unroll
        for (int ks = 0; ks < 8; ++ks) {
            const int colB = (lc + ks * 16) * 2;
            uint32_t ahf[2][4], alf[2][4];
            #pragma unroll
            for (int mt = 0; mt < 2; ++mt) {
                uint32_t off = swz256((uint32_t)((wm * 32 + mt * 16 + lr) * 256 + colB));
                ldmx4(ahf[mt], sb + AHs + off);
                ldmx4(alf[mt], sb + ALs + off);
            }
            #pragma unroll
            for (int ng = 0; ng < 2; ++ng) {
                uint32_t off = swz256((uint32_t)((wn * 32 + ng * 16 + lr) * 256 + colB));
                uint32_t vh4[4], vl4[4];
                ldmx4(vh4, sb + VHs + off);
                ldmx4(vl4, sb + VLs + off);
                #pragma unroll
                for (int mt = 0; mt < 2; ++mt) {
                    mma16816(o3[mt][2 * ng],     ahf[mt], vh4[0], vh4[2]);
                    mma16816(o3[mt][2 * ng + 1], ahf[mt], vh4[1], vh4[3]);
                    mma16816(o3[mt][2 * ng],     ahf[mt], vl4[0], vl4[2]);
                    mma16816(o3[mt][2 * ng + 1], ahf[mt], vl4[1], vl4[3]);
                    mma16816(o3[mt][2 * ng],     alf[mt], vh4[0], vh4[2]);
                    mma16816(o3[mt][2 * ng + 1], alf[mt], vh4[1], vh4[3]);
                }
            }
        }

        // Epilogue: O chunk to gmem (float2 per thread element pair)
        #pragma unroll
        for (int mt = 0; mt < 2; ++mt)
            #pragma unroll
            for (int nt = 0; nt < 4; ++nt)
                #pragma unroll
                for (int rh = 0; rh < 2; ++rh) {
                    int row = wm * 32 + mt * 16 + rh * 8 + g;
                    int col = nc * 64 + wn * 32 + nt * 8 + 2 * tg;
                    *reinterpret_cast<float2*>(Out + base + (long)row * Ee + col) =
                        make_float2(o3[mt][nt][rh * 2], o3[mt][nt][rh * 2 + 1]);
                }
        __syncthreads();
    }
}

extern "C" void kernel_launch(void* const* d_in, const int* in_sizes, int n_in,
                              void* d_out, int out_size)
{
    const float* Q = (const float*)d_in[0];
    const float* K = (const float*)d_in[1];
    const float* V = (const float*)d_in[2];
    float* out = (float*)d_out;

    const int b = in_sizes[0] / (Tt * Ee);
    const long out_elems = (long)b * Tt * Ee;
    const long a_elems   = (long)b * Tt * BSz;
    float* Afl = ((long)out_size >= out_elems + a_elems) ? (out + out_elems) : nullptr;

    cudaFuncSetAttribute(diag_block_attn_mma,
                         cudaFuncAttributeMaxDynamicSharedMemorySize, SMEM_BYTES);
    dim3 grid(NBk, b);
    diag_block_attn_mma<<<grid, 256, SMEM_BYTES>>>(Q, K, V, out, Afl);
}

// round 6
// speedup vs baseline: 2.3596x; 1.0557x over previous
#include <cuda_runtime.h>
#include <cuda_bf16.h>
#include <cstdint>
#include <math.h>

// DiagBlockAttention b=16,t=8192,e=256,block=128 — mma.sync bf16 hi/lo split,
// double-buffered staging pipeline.
// d_out = O [b,t,256] fp32 ++ A_flat [b,t,128] fp32.

namespace {
constexpr int Tt = 8192, Ee = 256, BSz = 128, NBk = 64;
constexpr float SCALE = 0.0625f;
constexpr int EC = 32;           // phase-1 e-chunk
constexpr int VC = 32;           // phase-3 e-chunk

// SMEM byte map
constexpr int RED_M = 0;         // 256 f32
constexpr int RED_S = 1024;      // 256 f32
constexpr int REG0  = 2048;
// phase 1: double-buffered Q/K hi/lo tiles [128 r][32 c] bf16, 64B rows (swz64)
//   per buffer: QH +0, QL +8192, KH +16384, KL +24576 ; buffer stride 32768
// phase 2/3: A hi/lo [128 m][128 k] bf16, 256B rows (swz256) — overlaps P1 bufs
constexpr int AHs = REG0, ALs = REG0 + 32768;
// phase 3: double-buffered V^T hi/lo [32 e][128 tok] bf16, 256B rows (swz256)
//   per buffer: VH +0, VL +8192 ; buffer stride 16384
constexpr int VB0 = REG0 + 65536;
constexpr int SMEM_BYTES = REG0 + 98304;   // 100352 -> 2 CTAs/SM
}

__device__ __forceinline__ uint32_t swz64(uint32_t o)  { return o ^ ((o >> 3) & 0x30u); }
__device__ __forceinline__ uint32_t swz256(uint32_t o) { return o ^ ((o >> 4) & 0x70u); }

__device__ __forceinline__ uint32_t smem_u32(const void* p) {
    uint32_t a;
    asm("{ .reg .u64 t; cvta.to.shared.u64 t, %1; cvt.u32.u64 %0, t; }" : "=r"(a) : "l"(p));
    return a;
}

__device__ __forceinline__ void ldmx4(uint32_t r[4], uint32_t addr) {
    asm volatile("ldmatrix.sync.aligned.m8n8.x4.shared.b16 {%0,%1,%2,%3}, [%4];"
                 : "=r"(r[0]), "=r"(r[1]), "=r"(r[2]), "=r"(r[3]) : "r"(addr));
}

__device__ __forceinline__ void mma16816(float c[4], const uint32_t a[4],
                                         uint32_t b0, uint32_t b1) {
    asm volatile("mma.sync.aligned.m16n8k16.row.col.f32.bf16.bf16.f32 "
                 "{%0,%1,%2,%3},{%4,%5,%6,%7},{%8,%9},{%0,%1,%2,%3};"
                 : "+f"(c[0]), "+f"(c[1]), "+f"(c[2]), "+f"(c[3])
                 : "r"(a[0]), "r"(a[1]), "r"(a[2]), "r"(a[3]), "r"(b0), "r"(b1));
}

// Split two fp32 into packed bf16x2 hi and lo (residual) parts.
__device__ __forceinline__ void split2(float x, float y, uint32_t& H, uint32_t& L) {
    __nv_bfloat16 hx = __float2bfloat16(x), hy = __float2bfloat16(y);
    __nv_bfloat16 lx = __float2bfloat16(x - __bfloat162float(hx));
    __nv_bfloat16 ly = __float2bfloat16(y - __bfloat162float(hy));
    __nv_bfloat162 Hp(hx, hy), Lp(lx, ly);
    H = *reinterpret_cast<uint32_t*>(&Hp);
    L = *reinterpret_cast<uint32_t*>(&Lp);
}

__global__ void __launch_bounds__(256, 2)
diag_block_attn_mma(const float* __restrict__ Q, const float* __restrict__ K,
                    const float* __restrict__ V, float* __restrict__ Out,
                    float* __restrict__ Afl)
{
    extern __shared__ char smc[];
    const uint32_t sb = smem_u32(smc);
    float* redM = reinterpret_cast<float*>(smc + RED_M);
    float* redS = reinterpret_cast<float*>(smc + RED_S);

    const int tid = threadIdx.x;
    const int wid = tid >> 5;
    const int lid = tid & 31;
    const int g   = lid >> 2;
    const int tg  = lid & 3;
    const int wm  = wid >> 1;        // warp row (0..3): rows wm*32..+31
    const int wn  = wid & 1;         // warp col (0..1)
    const int lr  = lid & 15;
    const int lc  = (lid >> 4) * 8;  // ldmatrix col-block (elements)
    const int n   = blockIdx.x;
    const int b   = blockIdx.y;
    const long base = ((long)b * Tt + (long)n * BSz) * Ee;

    // ---- phase-1 staging: chunk c (32 e) -> buffer bs ----
    auto stage1 = [&](int c, int bs) {
        const float* Qg = Q + base + c * EC;
        const float* Kg = K + base + c * EC;
        char* bb = smc + REG0 + bs * 32768;
        #pragma unroll
        for (int u = 0; u < 4; ++u) {
            int idx = tid + 256 * u;       // 0..1023
            int r   = idx >> 3;            // 0..127
            int ce  = (idx & 7) << 2;      // 0..28
            float4 q = *reinterpret_cast<const float4*>(Qg + (long)r * Ee + ce);
            float4 k = *reinterpret_cast<const float4*>(Kg + (long)r * Ee + ce);
            uint32_t qh0, ql0, qh1, ql1, kh0, kl0, kh1, kl1;
            split2(q.x, q.y, qh0, ql0); split2(q.z, q.w, qh1, ql1);
            split2(k.x, k.y, kh0, kl0); split2(k.z, k.w, kh1, kl1);
            uint32_t off = swz64((uint32_t)(r * 64 + ce * 2));
            *reinterpret_cast<uint2*>(bb + off)         = make_uint2(qh0, qh1);
            *reinterpret_cast<uint2*>(bb + 8192 + off)  = make_uint2(ql0, ql1);
            *reinterpret_cast<uint2*>(bb + 16384 + off) = make_uint2(kh0, kh1);
            *reinterpret_cast<uint2*>(bb + 24576 + off) = make_uint2(kl0, kl1);
        }
    };

    // ---- phase-3 V staging: chunk nc (32 e) -> buffer bs (transposed) ----
    auto stage3 = [&](int nc, int bs) {
        char* bb = smc + VB0 + bs * 16384;
        #pragma unroll
        for (int u = 0; u < 2; ++u) {
            int unit = tid + 256 * u;       // 0..511
            int l    = unit & 31;
            int grp  = unit >> 5;           // 0..15
            int c4i  = grp & 7, khi = grp >> 3;
            int k    = 2 * l + 64 * khi;    // even token
            int e0   = 4 * c4i;
            const float* vg = V + base + (long)k * Ee + nc * VC + e0;
            float4 v0 = *reinterpret_cast<const float4*>(vg);
            float4 v1 = *reinterpret_cast<const float4*>(vg + Ee);
            const float* a0 = reinterpret_cast<const float*>(&v0);
            const float* a1 = reinterpret_cast<const float*>(&v1);
            #pragma unroll
            for (int j = 0; j < 4; ++j) {
                uint32_t H, L;
                split2(a0[j], a1[j], H, L);
                uint32_t off = swz256((uint32_t)((e0 + j) * 256 + k * 2));
                *reinterpret_cast<uint32_t*>(bb + off)        = H;
                *reinterpret_cast<uint32_t*>(bb + 8192 + off) = L;
            }
        }
    };

    // ================= Phase 1: S = Q K^T (3-pass hi/lo, pipelined) ==========
    float acc[2][8][4];
    #pragma unroll
    for (int mt = 0; mt < 2; ++mt)
        #pragma unroll
        for (int nt = 0; nt < 8; ++nt)
            #pragma unroll
            for (int cc = 0; cc < 4; ++cc) acc[mt][nt][cc] = 0.f;

    stage1(0, 0);
    __syncthreads();
    #pragma unroll 1
    for (int c = 0; c < 8; ++c) {
        if (c + 1 < 8) stage1(c + 1, (c + 1) & 1);
        const uint32_t bb = sb + REG0 + (c & 1) * 32768;
        #pragma unroll
        for (int ks = 0; ks < 2; ++ks) {
            const int colB = (lc + ks * 16) * 2;
            uint32_t qhf[2][4], qlf[2][4];
            #pragma unroll
            for (int mt = 0; mt < 2; ++mt) {
                uint32_t off = swz64((uint32_t)((wm * 32 + mt * 16 + lr) * 64 + colB));
                ldmx4(qhf[mt], bb + off);
                ldmx4(qlf[mt], bb + 8192 + off);
            }
            #pragma unroll
            for (int ng = 0; ng < 4; ++ng) {
                uint32_t off = swz64((uint32_t)((wn * 64 + ng * 16 + lr) * 64 + colB));
                uint32_t kh4[4], kl4[4];
                ldmx4(kh4, bb + 16384 + off);
                ldmx4(kl4, bb + 24576 + off);
                #pragma unroll
                for (int mt = 0; mt < 2; ++mt) {
                    mma16816(acc[mt][2 * ng],     qhf[mt], kh4[0], kh4[2]);
                    mma16816(acc[mt][2 * ng + 1], qhf[mt], kh4[1], kh4[3]);
                    mma16816(acc[mt][2 * ng],     qhf[mt], kl4[0], kl4[2]);
                    mma16816(acc[mt][2 * ng + 1], qhf[mt], kl4[1], kl4[3]);
                    mma16816(acc[mt][2 * ng],     qlf[mt], kh4[0], kh4[2]);
                    mma16816(acc[mt][2 * ng + 1], qlf[mt], kh4[1], kh4[3]);
                }
            }
        }
        __syncthreads();
    }

    // ================= Phase 2: mask + softmax =================
    float rmax[2][2] = {{-INFINITY, -INFINITY}, {-INFINITY, -INFINITY}};
    #pragma unroll
    for (int mt = 0; mt < 2; ++mt)
        #pragma unroll
        for (int nt = 0; nt < 8; ++nt)
            #pragma unroll
            for (int cc = 0; cc < 4; ++cc) {
                int row = wm * 32 + mt * 16 + (cc >> 1) * 8 + g;
                int col = wn * 64 + nt * 8 + 2 * tg + (cc & 1);
                float v = (col <= row) ? acc[mt][nt][cc] * SCALE : -INFINITY;
                acc[mt][nt][cc] = v;
                rmax[mt][cc >> 1] = fmaxf(rmax[mt][cc >> 1], v);
            }
    #pragma unroll
    for (int mt = 0; mt < 2; ++mt)
        #pragma unroll
        for (int rh = 0; rh < 2; ++rh) {
            float v = rmax[mt][rh];
            v = fmaxf(v, __shfl_xor_sync(0xffffffffu, v, 1));
            v = fmaxf(v, __shfl_xor_sync(0xffffffffu, v, 2));
            if (tg == 0) redM[wn * 128 + wm * 32 + mt * 16 + rh * 8 + g] = v;
        }

    // Pre-stage V chunk 0 (vbuf 0) — gmem latency hides behind softmax math.
    stage3(0, 0);
    __syncthreads();

    float rm[2][2], rsum[2][2] = {{0.f, 0.f}, {0.f, 0.f}};
    #pragma unroll
    for (int mt = 0; mt < 2; ++mt)
        #pragma unroll
        for (int rh = 0; rh < 2; ++rh) {
            int row = wm * 32 + mt * 16 + rh * 8 + g;
            rm[mt][rh] = fmaxf(redM[row], redM[128 + row]);
        }
    #pragma unroll
    for (int mt = 0; mt < 2; ++mt)
        #pragma unroll
        for (int nt = 0; nt < 8; ++nt)
            #pragma unroll
            for (int cc = 0; cc < 4; ++cc) {
                float p = __expf(acc[mt][nt][cc] - rm[mt][cc >> 1]);
                acc[mt][nt][cc] = p;
                rsum[mt][cc >> 1] += p;
            }
    #pragma unroll
    for (int mt = 0; mt < 2; ++mt)
        #pragma unroll
        for (int rh = 0; rh < 2; ++rh) {
            float s = rsum[mt][rh];
            s += __shfl_xor_sync(0xffffffffu, s, 1);
            s += __shfl_xor_sync(0xffffffffu, s, 2);
            if (tg == 0) redS[wn * 128 + wm * 32 + mt * 16 + rh * 8 + g] = s;
        }
    __syncthreads();

    float rinv[2][2];
    #pragma unroll
    for (int mt = 0; mt < 2; ++mt)
        #pragma unroll
        for (int rh = 0; rh < 2; ++rh) {
            int row = wm * 32 + mt * 16 + rh * 8 + g;
            rinv[mt][rh] = 1.f / (redS[row] + redS[128 + row]);
        }

    // Normalize; A -> gmem (fp32) and smem hi/lo bf16 (overwrites P1 buffers —
    // safe: all warps passed the redS barrier after their last P1 ldmatrix).
    #pragma unroll
    for (int mt = 0; mt < 2; ++mt)
        #pragma unroll
        for (int nt = 0; nt < 8; ++nt)
            #pragma unroll
            for (int rh = 0; rh < 2; ++rh) {
                float a0 = acc[mt][nt][rh * 2]     * rinv[mt][rh];
                float a1 = acc[mt][nt][rh * 2 + 1] * rinv[mt][rh];
                int row = wm * 32 + mt * 16 + rh * 8 + g;
                int col = wn * 64 + nt * 8 + 2 * tg;
                uint32_t H, L;
                split2(a0, a1, H, L);
                uint32_t off = swz256((uint32_t)(row * 256 + col * 2));
                *reinterpret_cast<uint32_t*>(smc + AHs + off) = H;
                *reinterpret_cast<uint32_t*>(smc + ALs + off) = L;
                if (Afl) {
                    *reinterpret_cast<float2*>(
                        Afl + ((long)b * Tt + (long)n * BSz + row) * BSz + col) =
                        make_float2(a0, a1);
                }
            }
    __syncthreads();   // A tiles + V chunk 0 ready

    // ================= Phase 3: O = A V (8 e-chunks of 32, pipelined) ========
    #pragma unroll 1
    for (int nc = 0; nc < 8; ++nc) {
        if (nc + 1 < 8) stage3(nc + 1, (nc + 1) & 1);
        const uint32_t vb = sb + VB0 + (nc & 1) * 16384;

        float o3[2][2][4];
        #pragma unroll
        for (int mt = 0; mt < 2; ++mt)
            #pragma unroll
            for (int nt = 0; nt < 2; ++nt)
                #pragma unroll
                for (int cc = 0; cc < 4; ++cc) o3[mt][nt][cc] = 0.f;

        #pragma unroll
        for (int ks = 0; ks < 8; ++ks) {
            const int colB = (lc + ks * 16) * 2;
            uint32_t ahf[2][4], alf[2][4];
            #pragma unroll
            for (int mt = 0; mt < 2; ++mt) {
                uint32_t off = swz256((uint32_t)((wm * 32 + mt * 16 + lr) * 256 + colB));
                ldmx4(ahf[mt], sb + AHs + off);
                ldmx4(alf[mt], sb + ALs + off);
            }
            uint32_t offv = swz256((uint32_t)((wn * 16 + lr) * 256 + colB));
            uint32_t vh4[4], vl4[4];
            ldmx4(vh4, vb + offv);
            ldmx4(vl4, vb + 8192 + offv);
            #pragma unroll
            for (int mt = 0; mt < 2; ++mt) {
                mma16816(o3[mt][0], ahf[mt], vh4[0], vh4[2]);
                mma16816(o3[mt][1], ahf[mt], vh4[1], vh4[3]);
                mma16816(o3[mt][0], ahf[mt], vl4[0], vl4[2]);
                mma16816(o3[mt][1], ahf[mt], vl4[1], vl4[3]);
                mma16816(o3[mt][0], alf[mt], vh4[0], vh4[2]);
                mma16816(o3[mt][1], alf[mt], vh4[1], vh4[3]);
            }
        }

        #pragma unroll
        for (int mt = 0; mt < 2; ++mt)
            #pragma unroll
            for (int nt = 0; nt < 2; ++nt)
                #pragma unroll
                for (int rh = 0; rh < 2; ++rh) {
                    int row = wm * 32 + mt * 16 + rh * 8 + g;
                    int col = nc * VC + wn * 16 + nt * 8 + 2 * tg;
                    *reinterpret_cast<float2*>(Out + base + (long)row * Ee + col) =
                        make_float2(o3[mt][nt][rh * 2], o3[mt][nt][rh * 2 + 1]);
                }
        __syncthreads();
    }
}

extern "C" void kernel_launch(void* const* d_in, const int* in_sizes, int n_in,
                              void* d_out, int out_size)
{
    const float* Q = (const float*)d_in[0];
    const float* K = (const float*)d_in[1];
    const float* V = (const float*)d_in[2];
    float* out = (float*)d_out;

    const int b = in_sizes[0] / (Tt * Ee);
    const long out_elems = (long)b * Tt * Ee;
    const long a_elems   = (long)b * Tt * BSz;
    float* Afl = ((long)out_size >= out_elems + a_elems) ? (out + out_elems) : nullptr;

    cudaFuncSetAttribute(diag_block_attn_mma,
                         cudaFuncAttributeMaxDynamicSharedMemorySize, SMEM_BYTES);
    dim3 grid(NBk, b);
    diag_block_attn_mma<<<grid, 256, SMEM_BYTES>>>(Q, K, V, out, Afl);
}